// round 2
// baseline (speedup 1.0000x reference)
#include <cuda_runtime.h>

// ---------------- problem constants ----------------
#define NZ     300
#define NX     400
#define NPML   32
#define NZP    (NZ + 2*NPML)            // 364
#define NXP    (NX + 2*NPML)            // 464
#define NXPP   480                      // pitch (floats)
#define NSTEPS 200
#define NSHOTS 2
#define DXC    0.01f
#define DTC    0.001f
#define SRC_Z  (NPML + 2)               // 34
#define REC_Z  (NPML + 2)               // 34

#define FSZ     (NZP * NXPP)            // 174720
#define TOTCELL (NSHOTS * FSZ)          // 349440

#define NBLK     148
#define NTHR     256
#define NTHREADS (NBLK * NTHR)          // 37888
#define MAXIT    ((TOTCELL + NTHREADS - 1) / NTHREADS)  // 10

// ---------------- device state (static, no allocs) ----------------
__device__ float g_lam[FSZ];
__device__ float g_lam2mu[FSZ];
__device__ float g_mu[FSZ];
__device__ float g_dtrho[FSZ];
__device__ float g_damp[FSZ];

__device__ float g_vx [NSHOTS][FSZ];
__device__ float g_vz [NSHOTS][FSZ];
__device__ float g_sxx[NSHOTS][FSZ];
__device__ float g_szz[NSHOTS][FSZ];
__device__ float g_sxz[NSHOTS][FSZ];

__device__ double   g_part[NBLK];
__device__ unsigned g_count = 0u;
__device__ volatile unsigned g_sense = 0u;

// ---------------- software grid barrier (sense reversal) ----------------
__device__ __forceinline__ void grid_sync(unsigned& local_sense)
{
    __syncthreads();
    if (threadIdx.x == 0) {
        unsigned ns = local_sense ^ 1u;
        __threadfence();
        if (atomicAdd(&g_count, 1u) == NBLK - 1u) {
            g_count = 0u;
            __threadfence();
            g_sense = ns;
        } else {
            while (g_sense != ns) __nanosleep(32);
        }
        __threadfence();
    }
    __syncthreads();
    local_sense ^= 1u;
}

// ---------------- persistent FDTD kernel ----------------
__global__ void __launch_bounds__(NTHR, 1)
fwi_persistent(const float* __restrict__ Vp,
               const float* __restrict__ Vs,
               const float* __restrict__ Den,
               const float* __restrict__ Stf,
               const float* __restrict__ Mask,
               const int*   __restrict__ ShotIds,
               float*       __restrict__ out)
{
    const int gtid = blockIdx.x * NTHR + threadIdx.x;
    unsigned local_sense = g_sense;   // stable between launches

    const float inv_dx = 1.0f / DXC;

    // ---------- prep: zero fields, coefficients, sponge ----------
    #pragma unroll
    for (int k = 0; k < MAXIT; ++k) {
        int cell = gtid + k * NTHREADS;
        if (cell < TOTCELL) {
            int s   = cell / FSZ;
            int rem = cell - s * FSZ;
            int i   = rem / NXPP;
            int j   = rem - i * NXPP;

            g_vx [s][rem] = 0.0f;
            g_vz [s][rem] = 0.0f;
            g_sxx[s][rem] = 0.0f;
            g_szz[s][rem] = 0.0f;
            g_sxz[s][rem] = 0.0f;

            if (s == 0) {
                if (j < NXP) {
                    int ip = i - NPML; ip = ip < 0 ? 0 : (ip > NZ - 1 ? NZ - 1 : ip);
                    int jp = j - NPML; jp = jp < 0 ? 0 : (jp > NX - 1 ? NX - 1 : jp);
                    float vp  = Vp [ip * NX + jp];
                    float vs  = Vs [ip * NX + jp];
                    float den = Den[ip * NX + jp];
                    float m   = Mask[i * NXP + j];
                    vp  = m * vp  + (1.0f - m) * vp;
                    vs  = m * vs  + (1.0f - m) * vs;
                    den = m * den + (1.0f - m) * den;

                    float mu  = vs * vs * den / 1000000.0f;
                    float lam = (vp * vp - 2.0f * vs * vs) * den / 1000000.0f;

                    g_lam[rem]    = lam;
                    g_mu[rem]     = mu;
                    g_lam2mu[rem] = lam + 2.0f * mu;
                    g_dtrho[rem]  = DTC / den;

                    float a1 = (float)(NPML - i);
                    float a2 = (float)(i - (NZP - 1 - NPML));
                    float dz = fmaxf(a1, a2); dz = fminf(fmaxf(dz, 0.0f), (float)NPML) / (float)NPML;
                    float b1 = (float)(NPML - j);
                    float b2 = (float)(j - (NXP - 1 - NPML));
                    float dxs = fmaxf(b1, b2); dxs = fminf(fmaxf(dxs, 0.0f), (float)NPML) / (float)NPML;
                    g_damp[rem] = expf(-0.1f * (dz * dz + dxs * dxs));
                } else {
                    g_lam[rem] = 0.0f; g_mu[rem] = 0.0f; g_lam2mu[rem] = 0.0f;
                    g_dtrho[rem] = 0.0f; g_damp[rem] = 0.0f;
                }
            }
        }
    }

    const int sid0  = ShotIds[0];
    const int sid1  = ShotIds[1];
    const int srcx0 = NPML + 20 + sid0 * ((NX - 40) / NSHOTS);
    const int srcx1 = NPML + 20 + sid1 * ((NX - 40) / NSHOTS);

    grid_sync(local_sense);

    double acc = 0.0;

    // ---------- time loop ----------
    for (int t = 0; t < NSTEPS; ++t) {
        // ---- velocity update + receiver energy ----
        #pragma unroll
        for (int k = 0; k < MAXIT; ++k) {
            int cell = gtid + k * NTHREADS;
            if (cell >= TOTCELL) continue;
            int s   = cell / FSZ;
            int rem = cell - s * FSZ;
            int i   = rem / NXPP;
            int j   = rem - i * NXPP;
            if (j >= NXP) continue;

            const float* __restrict__ sxx = g_sxx[s];
            const float* __restrict__ szz = g_szz[s];
            const float* __restrict__ sxz = g_sxz[s];

            float damp  = g_damp[rem];
            float dtrho = g_dtrho[rem];

            float sxx_c = sxx[rem];
            float sxx_r = sxx[rem + 1];                         // pad col is 0
            float sxz_c = sxz[rem];
            float sxz_u = (i > 0)       ? sxz[rem - NXPP] : 0.0f;
            float sxz_l = (j > 0)       ? sxz[rem - 1]    : 0.0f;
            float szz_c = szz[rem];
            float szz_d = (i + 1 < NZP) ? szz[rem + NXPP] : 0.0f;

            float vx = (g_vx[s][rem] + dtrho * ((sxx_r - sxx_c) * inv_dx + (sxz_c - sxz_u) * inv_dx)) * damp;
            float vz = (g_vz[s][rem] + dtrho * ((sxz_c - sxz_l) * inv_dx + (szz_d - szz_c) * inv_dx)) * damp;

            g_vx[s][rem] = vx;
            g_vz[s][rem] = vz;

            if (i == REC_Z && j >= NPML && j < NPML + NX) {
                acc += (double)vx * (double)vx;
            }
        }

        grid_sync(local_sense);

        // ---- stress update + source injection ----
        #pragma unroll
        for (int k = 0; k < MAXIT; ++k) {
            int cell = gtid + k * NTHREADS;
            if (cell >= TOTCELL) continue;
            int s   = cell / FSZ;
            int rem = cell - s * FSZ;
            int i   = rem / NXPP;
            int j   = rem - i * NXPP;
            if (j >= NXP) continue;

            const float* __restrict__ vx = g_vx[s];
            const float* __restrict__ vz = g_vz[s];

            float damp = g_damp[rem];

            float vx_c = vx[rem];
            float vx_l = (j > 0)       ? vx[rem - 1]    : 0.0f;
            float vx_d = (i + 1 < NZP) ? vx[rem + NXPP] : 0.0f;
            float vz_c = vz[rem];
            float vz_u = (i > 0)       ? vz[rem - NXPP] : 0.0f;
            float vz_r = vz[rem + 1];                           // pad col is 0

            float dvxdx = (vx_c - vx_l) * inv_dx;
            float dvzdz = (vz_c - vz_u) * inv_dx;

            float lam    = g_lam[rem];
            float lam2mu = g_lam2mu[rem];
            float mu     = g_mu[rem];

            float sxxn = (g_sxx[s][rem] + DTC * (lam2mu * dvxdx + lam    * dvzdz)) * damp;
            float szzn = (g_szz[s][rem] + DTC * (lam    * dvxdx + lam2mu * dvzdz)) * damp;
            float sxzn = (g_sxz[s][rem] + DTC * mu * ((vx_d - vx_c) * inv_dx + (vz_r - vz_c) * inv_dx)) * damp;

            int sx = (s == 0) ? srcx0 : srcx1;
            if (i == SRC_Z && j == sx) {
                int sd = (s == 0) ? sid0 : sid1;
                float sv = Stf[sd * NSTEPS + t] * DTC;
                sxxn += sv;
                szzn += sv;
            }

            g_sxx[s][rem] = sxxn;
            g_szz[s][rem] = szzn;
            g_sxz[s][rem] = sxzn;
        }

        grid_sync(local_sense);
    }

    // ---------- deterministic reduction ----------
    __shared__ double sh[NTHR];
    sh[threadIdx.x] = acc;
    __syncthreads();
    for (int o = NTHR / 2; o > 0; o >>= 1) {
        if (threadIdx.x < o) sh[threadIdx.x] += sh[threadIdx.x + o];
        __syncthreads();
    }
    if (threadIdx.x == 0) g_part[blockIdx.x] = sh[0];

    grid_sync(local_sense);

    if (blockIdx.x == 0) {
        double a = (threadIdx.x < NBLK) ? g_part[threadIdx.x] : 0.0;
        sh[threadIdx.x] = a;
        __syncthreads();
        for (int o = NTHR / 2; o > 0; o >>= 1) {
            if (threadIdx.x < o) sh[threadIdx.x] += sh[threadIdx.x + o];
            __syncthreads();
        }
        if (threadIdx.x == 0) out[0] = (float)(0.5 * sh[0]);
    }
}

// ---------------- launcher ----------------
extern "C" void kernel_launch(void* const* d_in, const int* in_sizes, int n_in,
                              void* d_out, int out_size)
{
    const float* Vp      = (const float*)d_in[0];
    const float* Vs      = (const float*)d_in[1];
    const float* Den     = (const float*)d_in[2];
    const float* Stf     = (const float*)d_in[3];
    const float* Mask    = (const float*)d_in[4];
    const int*   ShotIds = (const int*)  d_in[5];
    float*       out     = (float*)d_out;
    (void)in_sizes; (void)n_in; (void)out_size;

    fwi_persistent<<<NBLK, NTHR>>>(Vp, Vs, Den, Stf, Mask, ShotIds, out);
}

// round 3
// speedup vs baseline: 2.0072x; 2.0072x over previous
#include <cuda_runtime.h>

// ---------------- problem constants ----------------
#define NZ     300
#define NX     400
#define NPML   32
#define NZP    (NZ + 2*NPML)            // 364
#define NXP    (NX + 2*NPML)            // 464
#define NXPP   480                      // row pitch in floats
#define NSTEPS 200
#define NSHOTS 2
#define DXC    0.01f
#define DTC    0.001f
#define SRC_Z  (NPML + 2)               // 34
#define REC_Z  (NPML + 2)               // 34

#define FSZ (NZP * NXPP)

#define BLKS_PER_SHOT 74
#define NBLK   (NSHOTS * BLKS_PER_SHOT) // 148
#define NTHR   1024
#define MAXC   3                        // max cells per thread (5*464/1024 -> 3)

// ---------------- device state (static, no allocs) ----------------
__device__ float g_vx [NSHOTS][FSZ];
__device__ float g_vz [NSHOTS][FSZ];
__device__ float g_sxx[NSHOTS][FSZ];
__device__ float g_szz[NSHOTS][FSZ];
__device__ float g_sxz[NSHOTS][FSZ];

__device__ unsigned g_flags[NBLK * 32];   // one flag per block, 128B apart
__device__ double   g_part[NBLK];
__device__ unsigned g_done = 0u;

// Publish own phase, then wait for neighbors to reach the same phase.
// Monotonic counters -> safe across graph replays (no reset race).
__device__ __forceinline__ void sync_neighbors(int b, int nb_lo, int nb_hi, unsigned q)
{
    __syncthreads();   // all threads of this block finished phase q
    if (threadIdx.x == 0) {
        __threadfence();                                   // writes -> visible before flag
        *(volatile unsigned*)&g_flags[b * 32] = q;         // publish
        if (nb_lo >= 0) {
            volatile unsigned* f = &g_flags[nb_lo * 32];
            while ((int)(*f - q) < 0) { }
        }
    }
    if (threadIdx.x == 1 && nb_hi >= 0) {
        volatile unsigned* f = &g_flags[nb_hi * 32];
        while ((int)(*f - q) < 0) { }
    }
    if (threadIdx.x < 2) __threadfence();                  // acquire + L1 invalidate
    __syncthreads();
}

__global__ void __launch_bounds__(NTHR, 1)
fwi_persistent(const float* __restrict__ Vp,
               const float* __restrict__ Vs,
               const float* __restrict__ Den,
               const float* __restrict__ Stf,
               const float* __restrict__ Mask,
               const int*   __restrict__ ShotIds,
               float*       __restrict__ out)
{
    const int b   = blockIdx.x;
    const int s   = b / BLKS_PER_SHOT;
    const int kk  = b - s * BLKS_PER_SHOT;
    const int z0  = (kk * NZP) / BLKS_PER_SHOT;
    const int z1  = ((kk + 1) * NZP) / BLKS_PER_SHOT;
    const int nrows  = z1 - z0;
    const int ncells = nrows * NXP;
    const int tid = threadIdx.x;

    const int nb_lo = (kk > 0)                 ? b - 1 : -1;
    const int nb_hi = (kk < BLKS_PER_SHOT - 1) ? b + 1 : -1;

    float* __restrict__ vxp  = g_vx [s];
    float* __restrict__ vzp  = g_vz [s];
    float* __restrict__ sxxp = g_sxx[s];
    float* __restrict__ szzp = g_szz[s];
    float* __restrict__ sxzp = g_sxz[s];

    const float inv_dx = 1.0f / DXC;

    // base phase from previous call (all blocks finish at the same value)
    unsigned q = *(volatile unsigned*)&g_flags[b * 32];

    // ---------- prep: zero own rows (incl. pitch pad cols) ----------
    {
        const int zc = nrows * NXPP;
        const int rb = z0 * NXPP;
        for (int c = tid; c < zc; c += NTHR) {
            int rem = rb + c;
            vxp[rem] = 0.0f; vzp[rem] = 0.0f;
            sxxp[rem] = 0.0f; szzp[rem] = 0.0f; sxzp[rem] = 0.0f;
        }
    }

    // ---------- per-thread cell list + register-resident coefficients ----------
    int   rm[MAXC], ci[MAXC], cj[MAXC];
    bool  val[MAXC];
    float cdamp[MAXC], cdtrho[MAXC], clam[MAXC], cl2mu[MAXC], cmu[MAXC];

    #pragma unroll
    for (int k = 0; k < MAXC; ++k) {
        int c = tid + k * NTHR;
        val[k] = (c < ncells);
        int cc = val[k] ? c : 0;
        int i = z0 + cc / NXP;
        int j = cc - (cc / NXP) * NXP;
        ci[k] = i; cj[k] = j;
        rm[k] = i * NXPP + j;

        int ip = min(max(i - NPML, 0), NZ - 1);
        int jp = min(max(j - NPML, 0), NX - 1);
        float vp  = Vp [ip * NX + jp];
        float vs  = Vs [ip * NX + jp];
        float den = Den[ip * NX + jp];
        float m   = Mask[i * NXP + j];
        vp  = m * vp  + (1.0f - m) * vp;
        vs  = m * vs  + (1.0f - m) * vs;
        den = m * den + (1.0f - m) * den;

        float mu  = vs * vs * den * 1e-6f;
        float lam = (vp * vp - 2.0f * vs * vs) * den * 1e-6f;
        cmu[k]    = mu;
        clam[k]   = lam;
        cl2mu[k]  = lam + 2.0f * mu;
        cdtrho[k] = DTC / den;

        float a1 = (float)(NPML - i);
        float a2 = (float)(i - (NZP - 1 - NPML));
        float dz = fmaxf(a1, a2); dz = fminf(fmaxf(dz, 0.0f), (float)NPML) / (float)NPML;
        float b1 = (float)(NPML - j);
        float b2 = (float)(j - (NXP - 1 - NPML));
        float dxs = fmaxf(b1, b2); dxs = fminf(fmaxf(dxs, 0.0f), (float)NPML) / (float)NPML;
        cdamp[k] = expf(-0.1f * (dz * dz + dxs * dxs));
    }

    const int   sid  = ShotIds[s];
    const int   srcx = NPML + 20 + sid * ((NX - 40) / NSHOTS);
    const float* stf = Stf + sid * NSTEPS;

    ++q;
    sync_neighbors(b, nb_lo, nb_hi, q);   // prep done (phase base+1)

    double acc = 0.0;

    // ---------------- time loop ----------------
    for (int t = 0; t < NSTEPS; ++t) {
        // ---- velocity half-step ----
        #pragma unroll
        for (int k = 0; k < MAXC; ++k) {
            if (!val[k]) continue;
            const int rem = rm[k];
            const int i = ci[k], j = cj[k];

            float sxx_c = sxxp[rem];
            float sxx_r = sxxp[rem + 1];                         // pad col stays 0
            float sxz_c = sxzp[rem];
            float sxz_u = (i > 0) ? sxzp[rem - NXPP] : 0.0f;
            float sxz_l = (i > 0 || j > 0) ? sxzp[rem - 1] : 0.0f; // row pad = 0
            float szz_c = szzp[rem];
            float szz_d = (i < NZP - 1) ? szzp[rem + NXPP] : 0.0f;

            float nvx = (vxp[rem] + cdtrho[k] * ((sxx_r - sxx_c) + (sxz_c - sxz_u)) * inv_dx) * cdamp[k];
            float nvz = (vzp[rem] + cdtrho[k] * ((sxz_c - sxz_l) + (szz_d - szz_c)) * inv_dx) * cdamp[k];

            vxp[rem] = nvx;
            vzp[rem] = nvz;

            if (i == REC_Z && j >= NPML && j < NPML + NX) {
                acc += (double)nvx * (double)nvx;
            }
        }

        ++q;
        sync_neighbors(b, nb_lo, nb_hi, q);

        // ---- stress half-step ----
        #pragma unroll
        for (int k = 0; k < MAXC; ++k) {
            if (!val[k]) continue;
            const int rem = rm[k];
            const int i = ci[k], j = cj[k];

            float vx_c = vxp[rem];
            float vx_l = (i > 0 || j > 0) ? vxp[rem - 1] : 0.0f;
            float vx_d = (i < NZP - 1) ? vxp[rem + NXPP] : 0.0f;
            float vz_c = vzp[rem];
            float vz_u = (i > 0) ? vzp[rem - NXPP] : 0.0f;
            float vz_r = vzp[rem + 1];                           // pad col stays 0

            float dvxdx = (vx_c - vx_l) * inv_dx;
            float dvzdz = (vz_c - vz_u) * inv_dx;

            float sxxn = (sxxp[rem] + DTC * (cl2mu[k] * dvxdx + clam[k]  * dvzdz)) * cdamp[k];
            float szzn = (szzp[rem] + DTC * (clam[k]  * dvxdx + cl2mu[k] * dvzdz)) * cdamp[k];
            float sxzn = (sxzp[rem] + DTC * cmu[k] * ((vx_d - vx_c) + (vz_r - vz_c)) * inv_dx) * cdamp[k];

            if (i == SRC_Z && j == srcx) {
                float sv = stf[t] * DTC;
                sxxn += sv;
                szzn += sv;
            }

            sxxp[rem] = sxxn;
            szzp[rem] = szzn;
            sxzp[rem] = sxzn;
        }

        ++q;
        sync_neighbors(b, nb_lo, nb_hi, q);
    }

    // ---------------- reduction ----------------
    __shared__ double sh[NTHR];
    sh[tid] = acc;
    __syncthreads();
    for (int o = NTHR / 2; o > 0; o >>= 1) {
        if (tid < o) sh[tid] += sh[tid + o];
        __syncthreads();
    }

    __shared__ int is_last;
    if (tid == 0) {
        g_part[b] = sh[0];
        __threadfence();
        unsigned ticket = atomicAdd(&g_done, 1u);
        is_last = ((ticket + 1u) % NBLK == 0u) ? 1 : 0;
    }
    __syncthreads();

    if (is_last) {
        __threadfence();
        double a = 0.0;
        if (tid < NBLK) a = __ldcg(&g_part[tid]);
        sh[tid] = a;
        __syncthreads();
        for (int o = NTHR / 2; o > 0; o >>= 1) {
            if (tid < o) sh[tid] += sh[tid + o];
            __syncthreads();
        }
        if (tid == 0) out[0] = (float)(0.5 * sh[0]);
    }
}

// ---------------- launcher ----------------
extern "C" void kernel_launch(void* const* d_in, const int* in_sizes, int n_in,
                              void* d_out, int out_size)
{
    const float* Vp      = (const float*)d_in[0];
    const float* Vs      = (const float*)d_in[1];
    const float* Den     = (const float*)d_in[2];
    const float* Stf     = (const float*)d_in[3];
    const float* Mask    = (const float*)d_in[4];
    const int*   ShotIds = (const int*)  d_in[5];
    float*       out     = (float*)d_out;
    (void)in_sizes; (void)n_in; (void)out_size;

    fwi_persistent<<<NBLK, NTHR>>>(Vp, Vs, Den, Stf, Mask, ShotIds, out);
}